// round 14
// baseline (speedup 1.0000x reference)
#include <cuda_runtime.h>
#include <stdint.h>

#define BB    32
#define NBOX  8192
#define MGT   256
#define NP    8448        // NBOX + MGT
#define NSAMP 512
#define NFG   128
#define KBIN  256
#define KCAP  4096
#define LCAP  256
#define BCAP  2048
#define THRESH (1u << 20)            // keep negatives with inv_m < 2^20 (r > 0.875)
#define MASK37 ((1ull << 37) - 1)

// scratch (device globals -- no allocation allowed; zero-initialized at load;
// k2 resets g_cnt/g_bandcnt each run; g_gcnt is plain-stored each run)
__device__ unsigned long long g_sel[BB * KCAP];
__device__ unsigned int       g_cnt[BB];
__device__ unsigned int       g_bandcnt[BB * 8];
__device__ float4             g_bbox[BB * 8 * BCAP];     // band-packed boxes
__device__ unsigned short     g_bidx[BB * 8 * BCAP];     // original indices
__device__ float4             g_gbox[BB * 8 * MGT];      // per-band candidate gts
__device__ float              g_garea[BB * 8 * MGT];
__device__ unsigned short     g_ggid[BB * 8 * MGT];
__device__ unsigned int       g_gcnt[BB * 8];

__device__ __forceinline__ uint32_t rotl32(uint32_t x, int d) {
    return (x << d) | (x >> (32 - d));
}

// JAX *partitionable* threefry, key = (0, 42). bits(p) = x0 ^ x1 of
// threefry2x32((0,42), (0, p))
__device__ __forceinline__ uint32_t threefry_bits(uint32_t p) {
    const uint32_t ks0 = 0u, ks1 = 42u, ks2 = 0x1BD11BF0u;  // 0x1BD11BDA ^ 0 ^ 42
    uint32_t x0 = 0u + ks0;
    uint32_t x1 = p + ks1;
#define TF_R(r) { x0 += x1; x1 = rotl32(x1, (r)); x1 ^= x0; }
    TF_R(13) TF_R(15) TF_R(26) TF_R(6)   x0 += ks1; x1 += ks2 + 1u;
    TF_R(17) TF_R(29) TF_R(16) TF_R(24)  x0 += ks2; x1 += ks0 + 2u;
    TF_R(13) TF_R(15) TF_R(26) TF_R(6)   x0 += ks0; x1 += ks1 + 3u;
    TF_R(17) TF_R(29) TF_R(16) TF_R(24)  x0 += ks1; x1 += ks2 + 4u;
    TF_R(13) TF_R(15) TF_R(26) TF_R(6)   x0 += ks2; x1 += ks0 + 5u;
#undef TF_R
    return x0 ^ x1;
}

// packed survivor word: [0:14) idx | [14:37) inv_m | bit37 pos | [38:46) mi
__device__ __forceinline__ void emit(int b, int i, bool pos, int mi) {
    uint32_t m = threefry_bits((uint32_t)(b * NP + i)) >> 9;
    uint32_t invm = 0x7FFFFFu - m;     // asc == r desc
    if (pos || invm < THRESH) {
        unsigned long long w = ((unsigned long long)(unsigned)mi << 38)
            | ((unsigned long long)(pos ? 1u : 0u) << 37)
            | ((unsigned long long)invm << 14) | (unsigned)i;
        unsigned j = atomicAdd(&g_cnt[b], 1u);
        if (j < KCAP) g_sel[b * KCAP + j] = w;
    }
}

// ---------------------------------------------------------------------------
// Kernel 0 (prep): grid (9, 32) x 256.
//  x<8 : bin 1024 boxes (4/thread, MLP 4) into band-packed g_bbox/g_bidx.
//  x==8: build per-band gt candidate lists (warp w = band w, ascending
//        ballot compaction) AND match the 256 gt-candidates (full loop).
// ---------------------------------------------------------------------------
__global__ __launch_bounds__(256)
void roi_prep_kernel(const float* __restrict__ boxes,
                     const float* __restrict__ gt_boxes) {
    const int b = blockIdx.y;
    const int s = blockIdx.x;
    const int t = threadIdx.x;
    const int lane = t & 31, wid = t >> 5;

    if (s < 8) {
        __shared__ unsigned scnt[8], sbase[8];
        if (t < 8) scnt[t] = 0u;
        __syncthreads();
        float4 A[4]; int bd[4]; unsigned lofs[4];
        const int base = s * 1024 + t;
#pragma unroll
        for (int k = 0; k < 4; ++k)
            A[k] = ((const float4*)boxes)[b * NBOX + base + k * 256];
#pragma unroll
        for (int k = 0; k < 4; ++k) {
            int d = (int)(A[k].x * 0.0078125f);   // exact: *2^-7, trunc
            bd[k] = d > 7 ? 7 : d;
            lofs[k] = atomicAdd(&scnt[bd[k]], 1u);
        }
        __syncthreads();
        if (t < 8) sbase[t] = atomicAdd(&g_bandcnt[b * 8 + t], scnt[t]);
        __syncthreads();
#pragma unroll
        for (int k = 0; k < 4; ++k) {
            unsigned pos = sbase[bd[k]] + lofs[k];
            if (pos < BCAP) {
                g_bbox[(b * 8 + bd[k]) * BCAP + pos] = A[k];
                g_bidx[(b * 8 + bd[k]) * BCAP + pos] = (unsigned short)(base + k * 256);
            }
        }
        return;
    }

    // ---- gt prep + gt-candidate matching ----
    __shared__ float4 sg[MGT];
    __shared__ float  sga[MGT];
    float4 g4 = ((const float4*)gt_boxes)[b * MGT + t];
    float mx = fmaxf(fmaxf(g4.x, g4.y), fmaxf(g4.z, g4.w));
    bool valid = (mx >= 0.0f);
    sg[t] = g4;
    sga[t] = (g4.z - g4.x) * (g4.w - g4.y);
    const int nv = __syncthreads_count(valid);   // valid gts are a prefix

    // warp w builds band w's candidate gt list, ascending
    {
        const float blo = (float)(wid * 128);
        const float bhi = blo + 264.0f;
        unsigned cnt = 0;
        for (int c = 0; c < MGT; c += 32) {
            int gi = c + lane;
            float4 gg = sg[gi];
            bool memb = (gi < nv) && (gg.z > blo) && (gg.x < bhi);
            unsigned mk = __ballot_sync(0xFFFFFFFFu, memb);
            if (memb) {
                unsigned slot = cnt + __popc(mk & ((1u << lane) - 1u));
                g_gbox[(b * 8 + wid) * MGT + slot]  = gg;
                g_garea[(b * 8 + wid) * MGT + slot] = sga[gi];
                g_ggid[(b * 8 + wid) * MGT + slot]  = (unsigned short)gi;
            }
            cnt += __popc(mk);
        }
        if (lane == 0) g_gcnt[b * 8 + wid] = cnt;   // plain store: replay-safe
    }

    // gt-candidate matching (full loop over valid prefix)
    {
        float4 A = sg[t];
        const float abA = sga[t];
        float biA = -1.0f, buA = 1.0f; int miA = 0;
#pragma unroll 4
        for (int g = 0; g < nv; ++g) {
            float4 gb = sg[g];
            float ga  = sga[g];
            float dy = fminf(A.z, gb.z) - fmaxf(A.x, gb.x);
            float dx = fminf(A.w, gb.w) - fmaxf(A.y, gb.y);
            if (dy > 0.0f && dx > 0.0f) {
                float inter = dy * dx;
                float uni   = (abA + ga) - inter;
                if (inter * buA > biA * uni) { biA = inter; buA = uni; miA = g; }
            }
        }
        bool posA = (biA > 0.0f) && (__fdiv_rn(biA, buA) >= 0.5f);
        emit(b, NBOX + t, posA, miA);
    }
}

// ---------------------------------------------------------------------------
// Kernel 1: pure band matching. grid (32, 16): band = y>>1, slice = y&1.
// Coalesced band-packed box reads, ~42 candidate gts in smem, frozen
// round-8 guarded 2-box update. Candidate list is an ascending exact
// superset of overlapping gts -> bit-identical argmax.
// ---------------------------------------------------------------------------
__global__ __launch_bounds__(256)
void roi_match_kernel(const float* __restrict__ boxes) {
    __shared__ float4 sgb[MGT];
    __shared__ float  sga2[MGT];
    __shared__ unsigned short sgid[MGT];

    const int b = blockIdx.x;
    const int band = blockIdx.y >> 1, slice = blockIdx.y & 1;
    const int t = threadIdx.x;

    const int ngl = (int)g_gcnt[b * 8 + band];
    if (t < ngl) {
        sgb[t]  = g_gbox[(b * 8 + band) * MGT + t];
        sga2[t] = g_garea[(b * 8 + band) * MGT + t];
        sgid[t] = g_ggid[(b * 8 + band) * MGT + t];
    }
    unsigned cnt = g_bandcnt[b * 8 + band];
    cnt = (cnt < BCAP) ? cnt : BCAP;
    __syncthreads();

    const unsigned half = (cnt + 1u) >> 1;
    const unsigned lob  = slice ? half : 0u;
    const unsigned end  = slice ? cnt : half;
    const float4* bb = &g_bbox[(b * 8 + band) * BCAP];
    const unsigned short* bi = &g_bidx[(b * 8 + band) * BCAP];

    for (unsigned chunk = lob; chunk < end; chunk += 512u) {
        unsigned pA = chunk + (unsigned)t, pB = pA + 256u;
        bool vA = pA < end, vB = pB < end;
        float4 A  = bb[vA ? pA : 0];
        float4 Bx = bb[vB ? pB : (vA ? pA : 0)];
        int iA = vA ? (int)bi[pA] : 0;
        int iB = vB ? (int)bi[pB] : 0;
        const float abA = (A.z - A.x) * (A.w - A.y);
        const float abB = (Bx.z - Bx.x) * (Bx.w - Bx.y);
        // bi=-1 sentinel: first overlapping gt always wins; bi>0 <=> overlap
        float biA = -1.0f, buA = 1.0f; int miA = 0;
        float biB = -1.0f, buB = 1.0f; int miB = 0;
#pragma unroll 4
        for (int j = 0; j < ngl; ++j) {
            float4 gb = sgb[j];
            float ga  = sga2[j];
            int gid   = (int)sgid[j];
            {
                float dy = fminf(A.z, gb.z) - fmaxf(A.x, gb.x);
                float dx = fminf(A.w, gb.w) - fmaxf(A.y, gb.y);
                if (dy > 0.0f && dx > 0.0f) {
                    float inter = dy * dx;
                    float uni   = (abA + ga) - inter;
                    if (inter * buA > biA * uni) { biA = inter; buA = uni; miA = gid; }
                }
            }
            {
                float dy = fminf(Bx.z, gb.z) - fmaxf(Bx.x, gb.x);
                float dx = fminf(Bx.w, gb.w) - fmaxf(Bx.y, gb.y);
                if (dy > 0.0f && dx > 0.0f) {
                    float inter = dy * dx;
                    float uni   = (abB + ga) - inter;
                    if (inter * buB > biB * uni) { biB = inter; buB = uni; miB = gid; }
                }
            }
        }
        if (vA) {
            bool posA = (biA > 0.0f) && (__fdiv_rn(biA, buA) >= 0.5f);
            emit(b, iA, posA, miA);
        }
        if (vB) {
            bool posB = (biB > 0.0f) && (__fdiv_rn(biB, buB) >= 0.5f);
            emit(b, iB, posB, miB);
        }
    }
}

// ---------------------------------------------------------------------------
// Kernel 2: per-image select over compacted survivors + 512-sort + gather.
// (round-11/13 version, verbatim; resets g_cnt/g_bandcnt) 32 CTAs x 512 thr.
// ---------------------------------------------------------------------------
__global__ __launch_bounds__(512)
void roi_sample_kernel(const float* __restrict__ boxes,
                       const float* __restrict__ gt_boxes,
                       const int*   __restrict__ gt_classes,
                       float* __restrict__ out) {
    extern __shared__ unsigned long long items[];   // KCAP
    __shared__ unsigned hP[KBIN], hN[KBIN], sPc[KBIN], sNc[KBIN];
    __shared__ unsigned wtP[8], wtN[8];
    __shared__ unsigned long long LP[LCAP], LN[LCAP], selk[NSAMP];
    __shared__ unsigned sh_bp, sh_bn, sh_befP, sh_befN;
    __shared__ unsigned cntP, cntN, cntS;
    __shared__ unsigned long long sh_KP, sh_KN;

    const int b = blockIdx.x;
    const int t = threadIdx.x;
    const int T = 512;
    const int lane = t & 31, wid = t >> 5;

    if (t == 0) { cntP = 0; cntN = 0; cntS = 0; sh_KP = MASK37; sh_KN = MASK37; }
    if (t < KBIN) { hP[t] = 0u; hN[t] = 0u; }
    const unsigned M0 = g_cnt[b];
    const unsigned M = (M0 < KCAP) ? M0 : KCAP;
    __syncthreads();
    if (t == 0) g_cnt[b] = 0u;          // reset for next replay
    if (t >= 32 && t < 40) g_bandcnt[b * 8 + (t - 32)] = 0u;

    // load survivors + histogram on inv_m[22:15]  (bits 29..36 of w)
    for (unsigned p = t; p < M; p += T) {
        unsigned long long w = g_sel[b * KCAP + p];
        items[p] = w;
        unsigned bin = (unsigned)(w >> 29) & 0xFFu;
        if ((w >> 37) & 1ull) atomicAdd(&hP[bin], 1u);
        else                  atomicAdd(&hN[bin], 1u);
    }
    __syncthreads();

    // inclusive scan of 256 bins: warp shuffles + tiny cross-warp combine
    unsigned sP = 0, sN = 0;
    if (t < KBIN) {
        sP = hP[t]; sN = hN[t];
#pragma unroll
        for (int off = 1; off < 32; off <<= 1) {
            unsigned vP = __shfl_up_sync(0xFFFFFFFFu, sP, off);
            unsigned vN = __shfl_up_sync(0xFFFFFFFFu, sN, off);
            if (lane >= off) { sP += vP; sN += vN; }
        }
        if (lane == 31) { wtP[wid] = sP; wtN[wid] = sN; }
    }
    __syncthreads();
    if (t < KBIN) {
        unsigned offP = 0, offN = 0;
        for (int ww = 0; ww < wid; ++ww) { offP += wtP[ww]; offN += wtN[ww]; }
        sPc[t] = sP + offP; sNc[t] = sN + offN;
    }
    __syncthreads();

    const unsigned total_pos = sPc[KBIN - 1];
    const unsigned n_pos = (total_pos < (unsigned)NFG) ? total_pos : (unsigned)NFG;
    const unsigned quota = (unsigned)NSAMP - n_pos;
    const bool needPsel = (total_pos > (unsigned)NFG);

    // boundary bins
    if (t < KBIN) {
        unsigned iP = sPc[t], pP = t ? sPc[t - 1] : 0u;
        unsigned iN = sNc[t], pN = t ? sNc[t - 1] : 0u;
        if (needPsel && iP >= (unsigned)NFG && pP < (unsigned)NFG) { sh_bp = (unsigned)t; sh_befP = pP; }
        if (iN >= quota && pN < quota) { sh_bn = (unsigned)t; sh_befN = pN; }
    }
    __syncthreads();

    // collect boundary-bin items (masked 37-bit keys)
    {
        unsigned bp = needPsel ? sh_bp : 0xFFFFFFFFu;
        unsigned bn = sh_bn;
        for (unsigned p = t; p < M; p += T) {
            unsigned long long w = items[p];
            unsigned bin = (unsigned)(w >> 29) & 0xFFu;
            if ((w >> 37) & 1ull) {
                if (bin == bp) { unsigned j = atomicAdd(&cntP, 1u); if (j < LCAP) LP[j] = w & MASK37; }
            } else {
                if (bin == bn) { unsigned j = atomicAdd(&cntN, 1u); if (j < LCAP) LN[j] = w & MASK37; }
            }
        }
    }
    selk[t] = ~0ull;
    __syncthreads();

    // exact rank within boundary bins -> cutoff keys (keys are unique)
    {
        unsigned cp = cntP < LCAP ? cntP : LCAP;
        unsigned cn = cntN < LCAP ? cntN : LCAP;
        if (needPsel && (unsigned)t < cp) {
            unsigned long long k = LP[t]; unsigned r = 0;
            for (unsigned l = 0; l < cp; ++l) r += (LP[l] < k);
            if (r == ((unsigned)NFG - sh_befP) - 1u) sh_KP = k;
        }
        if ((unsigned)t < cn) {
            unsigned long long k = LN[t]; unsigned r = 0;
            for (unsigned l = 0; l < cn; ++l) r += (LN[l] < k);
            if (r == (quota - sh_befN) - 1u) sh_KN = k;
        }
    }
    __syncthreads();

    // final selection (exactly 512); re-key by RNE-rounded score mantissa.
    // score = 2.0f + r rounds r's 23-bit mantissa m to 2^-22 grid:
    //   h = (m>>1) + ((m&1) & ((m>>1)&1)); ties broken by idx asc.
    {
        unsigned long long KP = sh_KP, KN = sh_KN;
        for (unsigned p = t; p < M; p += T) {
            unsigned long long w = items[p];
            unsigned long long kk = w & MASK37;
            bool sel = ((w >> 37) & 1ull) ? (kk <= KP) : (kk <= KN);
            if (sel) {
                unsigned mm = 0x7FFFFFu - (unsigned)((w >> 14) & 0x7FFFFFu);
                unsigned h  = (mm >> 1) + ((mm & 1u) & ((mm >> 1) & 1u));
                unsigned j  = atomicAdd(&cntS, 1u);
                selk[j] = (w & ~MASK37)                        // keep pos|mi high bits
                        | (((unsigned long long)(0x7FFFFFu - h)) << 14)
                        | (w & 0x3FFFull);
            }
        }
    }
    __syncthreads();

    // bitonic sort 512 keys by low 37 bits asc (== score desc, idx asc);
    // pos/mi ride in the high bits, masked out of comparisons via <<27.
    for (unsigned k = 2; k <= (unsigned)NSAMP; k <<= 1) {
        for (unsigned j = k >> 1; j > 0; j >>= 1) {
            unsigned p = (unsigned)t, q = p ^ j;
            if (q > p) {
                unsigned long long a = selk[p], c = selk[q];
                bool up = ((p & k) == 0);
                if (((a << 27) > (c << 27)) == up) { selk[p] = c; selk[q] = a; }
            }
            __syncthreads();
        }
    }

    // gather outputs
    {
        unsigned long long v = selk[t];
        if ((unsigned)t < cntS) {
            unsigned i  = (unsigned)(v & 0x3FFFu);
            bool pos    = (v >> 37) & 1ull;
            int  mi     = (int)((v >> 38) & 0xFFull);
            float4 roi = (i < NBOX)
                ? ((const float4*)boxes)[b * NBOX + i]
                : ((const float4*)gt_boxes)[b * MGT + (i - NBOX)];
            float4 gb = make_float4(0.f, 0.f, 0.f, 0.f);
            float cls = 0.0f, gidx = -1.0f;
            if (pos) {
                gb   = ((const float4*)gt_boxes)[b * MGT + mi];
                cls  = (float)gt_classes[b * MGT + mi];
                gidx = (float)mi;
            }
            size_t base = (size_t)(b * NSAMP + t);
            float* o1 = out + base * 4;                                   // rois
            o1[0] = roi.x; o1[1] = roi.y; o1[2] = roi.z; o1[3] = roi.w;
            float* o2 = out + (size_t)BB * NSAMP * 4 + base * 4;          // matched gt boxes
            o2[0] = gb.x; o2[1] = gb.y; o2[2] = gb.z; o2[3] = gb.w;
            out[(size_t)2 * BB * NSAMP * 4 + base] = cls;                 // classes
            out[(size_t)2 * BB * NSAMP * 4 + (size_t)BB * NSAMP + base] = gidx; // indices
        }
    }
}

extern "C" void kernel_launch(void* const* d_in, const int* in_sizes, int n_in,
                              void* d_out, int out_size) {
    (void)out_size;
    const float* boxes      = (const float*)d_in[0];
    const float* gt_boxes   = (const float*)d_in[1];
    const int*   gt_classes = (const int*)d_in[2];
    for (int k = 0; k < n_in; ++k) {
        if (in_sizes[k] == BB * NBOX * 4) boxes      = (const float*)d_in[k];
        else if (in_sizes[k] == BB * MGT * 4) gt_boxes = (const float*)d_in[k];
        else if (in_sizes[k] == BB * MGT)     gt_classes = (const int*)d_in[k];
    }
    float* out = (float*)d_out;

    dim3 g0(9, BB);
    roi_prep_kernel<<<g0, 256>>>(boxes, gt_boxes);

    dim3 g1(BB, 16);
    roi_match_kernel<<<g1, 256>>>(boxes);

    size_t smem = (size_t)KCAP * 8;   // 32 KB dynamic (items)
    cudaFuncSetAttribute(roi_sample_kernel,
                         cudaFuncAttributeMaxDynamicSharedMemorySize, (int)smem);
    roi_sample_kernel<<<BB, 512, smem>>>(boxes, gt_boxes, gt_classes, out);
}

// round 15
// speedup vs baseline: 1.2249x; 1.2249x over previous
#include <cuda_runtime.h>
#include <stdint.h>

#define BB    32
#define NBOX  8192
#define MGT   256
#define NP    8448        // NBOX + MGT
#define NSAMP 512
#define NFG   128
#define KBIN  256
#define KCAP  4096
#define LCAP  256
#define BCAP  2048
#define THRESH (1u << 20)            // keep negatives with inv_m < 2^20 (r > 0.875)
#define MASK37 ((1ull << 37) - 1)

// scratch (device globals -- no allocation allowed; zero-initialized at load;
// k2 resets g_cnt/g_bandcnt each run -> graph-replay safe)
__device__ unsigned long long g_sel[BB * KCAP];
__device__ unsigned int       g_cnt[BB];
__device__ unsigned int       g_bandcnt[BB * 8];
__device__ unsigned short     g_blist[BB * 8 * BCAP];

__device__ __forceinline__ uint32_t rotl32(uint32_t x, int d) {
    return (x << d) | (x >> (32 - d));
}

// JAX *partitionable* threefry, key = (0, 42). bits(p) = x0 ^ x1 of
// threefry2x32((0,42), (0, p))
__device__ __forceinline__ uint32_t threefry_bits(uint32_t p) {
    const uint32_t ks0 = 0u, ks1 = 42u, ks2 = 0x1BD11BF0u;  // 0x1BD11BDA ^ 0 ^ 42
    uint32_t x0 = 0u + ks0;
    uint32_t x1 = p + ks1;
#define TF_R(r) { x0 += x1; x1 = rotl32(x1, (r)); x1 ^= x0; }
    TF_R(13) TF_R(15) TF_R(26) TF_R(6)   x0 += ks1; x1 += ks2 + 1u;
    TF_R(17) TF_R(29) TF_R(16) TF_R(24)  x0 += ks2; x1 += ks0 + 2u;
    TF_R(13) TF_R(15) TF_R(26) TF_R(6)   x0 += ks0; x1 += ks1 + 3u;
    TF_R(17) TF_R(29) TF_R(16) TF_R(24)  x0 += ks1; x1 += ks2 + 4u;
    TF_R(13) TF_R(15) TF_R(26) TF_R(6)   x0 += ks2; x1 += ks0 + 5u;
#undef TF_R
    return x0 ^ x1;
}

// packed survivor word: [0:14) idx | [14:37) inv_m | bit37 pos | [38:46) mi
__device__ __forceinline__ void emit(int b, int i, bool pos, int mi) {
    uint32_t m = threefry_bits((uint32_t)(b * NP + i)) >> 9;
    uint32_t invm = 0x7FFFFFu - m;     // asc == r desc
    if (pos || invm < THRESH) {
        unsigned long long w = ((unsigned long long)(unsigned)mi << 38)
            | ((unsigned long long)(pos ? 1u : 0u) << 37)
            | ((unsigned long long)invm << 14) | (unsigned)i;
        unsigned j = atomicAdd(&g_cnt[b], 1u);
        if (j < KCAP) g_sel[b * KCAP + j] = w;
    }
}

// ---------------------------------------------------------------------------
// Kernel 0: bin boxes by y0 into 8 bands. 4 boxes/thread (MLP 4), reads only
// the y0 component (1 MB total). grid (8 slices, 32 images) x 256 threads.
// ---------------------------------------------------------------------------
__global__ __launch_bounds__(256)
void roi_bin_kernel(const float* __restrict__ boxes) {
    __shared__ unsigned scnt[8], sbase[8];
    const int b = blockIdx.y;
    const int base = blockIdx.x * 1024 + threadIdx.x;
    if (threadIdx.x < 8) scnt[threadIdx.x] = 0u;
    __syncthreads();
    float y0[4]; int bd[4]; unsigned lofs[4];
#pragma unroll
    for (int k = 0; k < 4; ++k)
        y0[k] = __ldg(&boxes[(size_t)(b * NBOX + base + k * 256) * 4]);
#pragma unroll
    for (int k = 0; k < 4; ++k) {
        int d = (int)(y0[k] * 0.0078125f);   // exact: *2^-7, trunc
        bd[k] = d > 7 ? 7 : d;
        lofs[k] = atomicAdd(&scnt[bd[k]], 1u);
    }
    __syncthreads();
    if (threadIdx.x < 8)
        sbase[threadIdx.x] = atomicAdd(&g_bandcnt[b * 8 + threadIdx.x], scnt[threadIdx.x]);
    __syncthreads();
#pragma unroll
    for (int k = 0; k < 4; ++k) {
        unsigned pos = sbase[bd[k]] + lofs[k];
        if (pos < BCAP)
            g_blist[(b * 8 + bd[k]) * BCAP + pos] = (unsigned short)(base + k * 256);
    }
}

// ---------------------------------------------------------------------------
// Kernel 1: max-IoU matching over band-pruned gt candidate lists.
// grid (32, 17): y<16 -> band = y>>1, slice = y&1 over that band's boxes;
// y==16 -> the 256 gt-candidates (full loop). 2 boxes/thread, guarded update
// (frozen round-8 form). Candidate list is an ascending-ordered exact
// superset of overlapping gts -> bit-identical argmax.
// ---------------------------------------------------------------------------
__global__ __launch_bounds__(256)
void roi_match_kernel(const float* __restrict__ boxes,
                      const float* __restrict__ gt_boxes) {
    __shared__ float4 sg[MGT];
    __shared__ float  sga[MGT];
    __shared__ unsigned short gl[MGT];
    __shared__ unsigned wscan[8];
    __shared__ unsigned sh_ngl;

    const int b = blockIdx.x;
    const int y = blockIdx.y;
    const int t = threadIdx.x;
    const int lane = t & 31, wid = t >> 5;

    float4 g4 = ((const float4*)gt_boxes)[b * MGT + t];
    float mx = fmaxf(fmaxf(g4.x, g4.y), fmaxf(g4.z, g4.w));
    bool valid = (mx >= 0.0f);
    sg[t] = g4;
    sga[t] = (g4.z - g4.x) * (g4.w - g4.y);
    const int nv = __syncthreads_count(valid);   // valid gts are a prefix

    if (y == 16) {
        // gt-candidates: full loop (tiny)
        float4 A = sg[t];
        const float abA = sga[t];
        float biA = -1.0f, buA = 1.0f; int miA = 0;
#pragma unroll 4
        for (int g = 0; g < nv; ++g) {
            float4 gb = sg[g];
            float ga  = sga[g];
            float dy = fminf(A.z, gb.z) - fmaxf(A.x, gb.x);
            float dx = fminf(A.w, gb.w) - fmaxf(A.y, gb.y);
            if (dy > 0.0f && dx > 0.0f) {
                float inter = dy * dx;
                float uni   = (abA + ga) - inter;
                if (inter * buA > biA * uni) { biA = inter; buA = uni; miA = g; }
            }
        }
        bool posA = (biA > 0.0f) && (__fdiv_rn(biA, buA) >= 0.5f);
        emit(b, NBOX + t, posA, miA);
        return;
    }

    const int band = y >> 1, slice = y & 1;
    const float blo = (float)(band * 128);
    const float bhi = blo + 264.0f;          // box y-extent within [blo, blo+264)

    // ascending-ordered compaction of candidate gts for this band
    bool memb = (t < nv) && (g4.z > blo) && (g4.x < bhi);
    unsigned mask = __ballot_sync(0xFFFFFFFFu, memb);
    if (lane == 0) wscan[wid] = __popc(mask);
    __syncthreads();
    if (t == 0) {
        unsigned s = 0;
        for (int i2 = 0; i2 < 8; ++i2) { unsigned c = wscan[i2]; wscan[i2] = s; s += c; }
        sh_ngl = s;
    }
    __syncthreads();
    if (memb) gl[wscan[wid] + __popc(mask & ((1u << lane) - 1u))] = (unsigned short)t;
    const int ngl = (int)sh_ngl;
    __syncthreads();

    unsigned cnt = g_bandcnt[b * 8 + band];
    cnt = (cnt < BCAP) ? cnt : BCAP;
    const unsigned half = (cnt + 1u) >> 1;
    const unsigned lob  = slice ? half : 0u;
    const unsigned end  = slice ? cnt : half;
    const unsigned short* list = &g_blist[(b * 8 + band) * BCAP];

    for (unsigned chunk = lob; chunk < end; chunk += 512u) {
        unsigned pA = chunk + (unsigned)t, pB = pA + 256u;
        bool vA = pA < end, vB = pB < end;
        int iA = vA ? (int)list[pA] : 0;
        int iB = vB ? (int)list[pB] : iA;
        float4 A  = ((const float4*)boxes)[b * NBOX + iA];
        float4 Bx = ((const float4*)boxes)[b * NBOX + iB];
        const float abA = (A.z - A.x) * (A.w - A.y);
        const float abB = (Bx.z - Bx.x) * (Bx.w - Bx.y);
        float biA = -1.0f, buA = 1.0f; int miA = 0;
        float biB = -1.0f, buB = 1.0f; int miB = 0;
#pragma unroll 4
        for (int g = 0; g < ngl; ++g) {
            int gid = (int)gl[g];                // uniform broadcast
            float4 gb = sg[gid];
            float ga  = sga[gid];
            {
                float dy = fminf(A.z, gb.z) - fmaxf(A.x, gb.x);
                float dx = fminf(A.w, gb.w) - fmaxf(A.y, gb.y);
                if (dy > 0.0f && dx > 0.0f) {
                    float inter = dy * dx;
                    float uni   = (abA + ga) - inter;
                    if (inter * buA > biA * uni) { biA = inter; buA = uni; miA = gid; }
                }
            }
            {
                float dy = fminf(Bx.z, gb.z) - fmaxf(Bx.x, gb.x);
                float dx = fminf(Bx.w, gb.w) - fmaxf(Bx.y, gb.y);
                if (dy > 0.0f && dx > 0.0f) {
                    float inter = dy * dx;
                    float uni   = (abB + ga) - inter;
                    if (inter * buB > biB * uni) { biB = inter; buB = uni; miB = gid; }
                }
            }
        }
        if (vA) {
            bool posA = (biA > 0.0f) && (__fdiv_rn(biA, buA) >= 0.5f);
            emit(b, iA, posA, miA);
        }
        if (vB) {
            bool posB = (biB > 0.0f) && (__fdiv_rn(biB, buB) >= 0.5f);
            emit(b, iB, posB, miB);
        }
    }
}

// ---------------------------------------------------------------------------
// Kernel 2: per-image select over compacted survivors + 512-sort + gather.
// (round-11/13 version, verbatim; resets g_cnt/g_bandcnt) 32 CTAs x 512 thr.
// ---------------------------------------------------------------------------
__global__ __launch_bounds__(512)
void roi_sample_kernel(const float* __restrict__ boxes,
                       const float* __restrict__ gt_boxes,
                       const int*   __restrict__ gt_classes,
                       float* __restrict__ out) {
    extern __shared__ unsigned long long items[];   // KCAP
    __shared__ unsigned hP[KBIN], hN[KBIN], sPc[KBIN], sNc[KBIN];
    __shared__ unsigned wtP[8], wtN[8];
    __shared__ unsigned long long LP[LCAP], LN[LCAP], selk[NSAMP];
    __shared__ unsigned sh_bp, sh_bn, sh_befP, sh_befN;
    __shared__ unsigned cntP, cntN, cntS;
    __shared__ unsigned long long sh_KP, sh_KN;

    const int b = blockIdx.x;
    const int t = threadIdx.x;
    const int T = 512;
    const int lane = t & 31, wid = t >> 5;

    if (t == 0) { cntP = 0; cntN = 0; cntS = 0; sh_KP = MASK37; sh_KN = MASK37; }
    if (t < KBIN) { hP[t] = 0u; hN[t] = 0u; }
    const unsigned M0 = g_cnt[b];
    const unsigned M = (M0 < KCAP) ? M0 : KCAP;
    __syncthreads();
    if (t == 0) g_cnt[b] = 0u;          // reset for next replay
    if (t >= 32 && t < 40) g_bandcnt[b * 8 + (t - 32)] = 0u;

    // load survivors + histogram on inv_m[22:15]  (bits 29..36 of w)
    for (unsigned p = t; p < M; p += T) {
        unsigned long long w = g_sel[b * KCAP + p];
        items[p] = w;
        unsigned bin = (unsigned)(w >> 29) & 0xFFu;
        if ((w >> 37) & 1ull) atomicAdd(&hP[bin], 1u);
        else                  atomicAdd(&hN[bin], 1u);
    }
    __syncthreads();

    // inclusive scan of 256 bins: warp shuffles + tiny cross-warp combine
    unsigned sP = 0, sN = 0;
    if (t < KBIN) {
        sP = hP[t]; sN = hN[t];
#pragma unroll
        for (int off = 1; off < 32; off <<= 1) {
            unsigned vP = __shfl_up_sync(0xFFFFFFFFu, sP, off);
            unsigned vN = __shfl_up_sync(0xFFFFFFFFu, sN, off);
            if (lane >= off) { sP += vP; sN += vN; }
        }
        if (lane == 31) { wtP[wid] = sP; wtN[wid] = sN; }
    }
    __syncthreads();
    if (t < KBIN) {
        unsigned offP = 0, offN = 0;
        for (int ww = 0; ww < wid; ++ww) { offP += wtP[ww]; offN += wtN[ww]; }
        sPc[t] = sP + offP; sNc[t] = sN + offN;
    }
    __syncthreads();

    const unsigned total_pos = sPc[KBIN - 1];
    const unsigned n_pos = (total_pos < (unsigned)NFG) ? total_pos : (unsigned)NFG;
    const unsigned quota = (unsigned)NSAMP - n_pos;
    const bool needPsel = (total_pos > (unsigned)NFG);

    // boundary bins
    if (t < KBIN) {
        unsigned iP = sPc[t], pP = t ? sPc[t - 1] : 0u;
        unsigned iN = sNc[t], pN = t ? sNc[t - 1] : 0u;
        if (needPsel && iP >= (unsigned)NFG && pP < (unsigned)NFG) { sh_bp = (unsigned)t; sh_befP = pP; }
        if (iN >= quota && pN < quota) { sh_bn = (unsigned)t; sh_befN = pN; }
    }
    __syncthreads();

    // collect boundary-bin items (masked 37-bit keys)
    {
        unsigned bp = needPsel ? sh_bp : 0xFFFFFFFFu;
        unsigned bn = sh_bn;
        for (unsigned p = t; p < M; p += T) {
            unsigned long long w = items[p];
            unsigned bin = (unsigned)(w >> 29) & 0xFFu;
            if ((w >> 37) & 1ull) {
                if (bin == bp) { unsigned j = atomicAdd(&cntP, 1u); if (j < LCAP) LP[j] = w & MASK37; }
            } else {
                if (bin == bn) { unsigned j = atomicAdd(&cntN, 1u); if (j < LCAP) LN[j] = w & MASK37; }
            }
        }
    }
    selk[t] = ~0ull;
    __syncthreads();

    // exact rank within boundary bins -> cutoff keys (keys are unique)
    {
        unsigned cp = cntP < LCAP ? cntP : LCAP;
        unsigned cn = cntN < LCAP ? cntN : LCAP;
        if (needPsel && (unsigned)t < cp) {
            unsigned long long k = LP[t]; unsigned r = 0;
            for (unsigned l = 0; l < cp; ++l) r += (LP[l] < k);
            if (r == ((unsigned)NFG - sh_befP) - 1u) sh_KP = k;
        }
        if ((unsigned)t < cn) {
            unsigned long long k = LN[t]; unsigned r = 0;
            for (unsigned l = 0; l < cn; ++l) r += (LN[l] < k);
            if (r == (quota - sh_befN) - 1u) sh_KN = k;
        }
    }
    __syncthreads();

    // final selection (exactly 512); re-key by RNE-rounded score mantissa.
    // score = 2.0f + r rounds r's 23-bit mantissa m to 2^-22 grid:
    //   h = (m>>1) + ((m&1) & ((m>>1)&1)); ties broken by idx asc.
    {
        unsigned long long KP = sh_KP, KN = sh_KN;
        for (unsigned p = t; p < M; p += T) {
            unsigned long long w = items[p];
            unsigned long long kk = w & MASK37;
            bool sel = ((w >> 37) & 1ull) ? (kk <= KP) : (kk <= KN);
            if (sel) {
                unsigned mm = 0x7FFFFFu - (unsigned)((w >> 14) & 0x7FFFFFu);
                unsigned h  = (mm >> 1) + ((mm & 1u) & ((mm >> 1) & 1u));
                unsigned j  = atomicAdd(&cntS, 1u);
                selk[j] = (w & ~MASK37)                        // keep pos|mi high bits
                        | (((unsigned long long)(0x7FFFFFu - h)) << 14)
                        | (w & 0x3FFFull);
            }
        }
    }
    __syncthreads();

    // bitonic sort 512 keys by low 37 bits asc (== score desc, idx asc);
    // pos/mi ride in the high bits, masked out of comparisons via <<27.
    for (unsigned k = 2; k <= (unsigned)NSAMP; k <<= 1) {
        for (unsigned j = k >> 1; j > 0; j >>= 1) {
            unsigned p = (unsigned)t, q = p ^ j;
            if (q > p) {
                unsigned long long a = selk[p], c = selk[q];
                bool up = ((p & k) == 0);
                if (((a << 27) > (c << 27)) == up) { selk[p] = c; selk[q] = a; }
            }
            __syncthreads();
        }
    }

    // gather outputs
    {
        unsigned long long v = selk[t];
        if ((unsigned)t < cntS) {
            unsigned i  = (unsigned)(v & 0x3FFFu);
            bool pos    = (v >> 37) & 1ull;
            int  mi     = (int)((v >> 38) & 0xFFull);
            float4 roi = (i < NBOX)
                ? ((const float4*)boxes)[b * NBOX + i]
                : ((const float4*)gt_boxes)[b * MGT + (i - NBOX)];
            float4 gb = make_float4(0.f, 0.f, 0.f, 0.f);
            float cls = 0.0f, gidx = -1.0f;
            if (pos) {
                gb   = ((const float4*)gt_boxes)[b * MGT + mi];
                cls  = (float)gt_classes[b * MGT + mi];
                gidx = (float)mi;
            }
            size_t base = (size_t)(b * NSAMP + t);
            float* o1 = out + base * 4;                                   // rois
            o1[0] = roi.x; o1[1] = roi.y; o1[2] = roi.z; o1[3] = roi.w;
            float* o2 = out + (size_t)BB * NSAMP * 4 + base * 4;          // matched gt boxes
            o2[0] = gb.x; o2[1] = gb.y; o2[2] = gb.z; o2[3] = gb.w;
            out[(size_t)2 * BB * NSAMP * 4 + base] = cls;                 // classes
            out[(size_t)2 * BB * NSAMP * 4 + (size_t)BB * NSAMP + base] = gidx; // indices
        }
    }
}

extern "C" void kernel_launch(void* const* d_in, const int* in_sizes, int n_in,
                              void* d_out, int out_size) {
    (void)out_size;
    const float* boxes      = (const float*)d_in[0];
    const float* gt_boxes   = (const float*)d_in[1];
    const int*   gt_classes = (const int*)d_in[2];
    for (int k = 0; k < n_in; ++k) {
        if (in_sizes[k] == BB * NBOX * 4) boxes      = (const float*)d_in[k];
        else if (in_sizes[k] == BB * MGT * 4) gt_boxes = (const float*)d_in[k];
        else if (in_sizes[k] == BB * MGT)     gt_classes = (const int*)d_in[k];
    }
    float* out = (float*)d_out;

    dim3 g0(8, BB);
    roi_bin_kernel<<<g0, 256>>>(boxes);

    dim3 g1(BB, 17);
    roi_match_kernel<<<g1, 256>>>(boxes, gt_boxes);

    size_t smem = (size_t)KCAP * 8;   // 32 KB dynamic (items)
    cudaFuncSetAttribute(roi_sample_kernel,
                         cudaFuncAttributeMaxDynamicSharedMemorySize, (int)smem);
    roi_sample_kernel<<<BB, 512, smem>>>(boxes, gt_boxes, gt_classes, out);
}